// round 2
// baseline (speedup 1.0000x reference)
#include <cuda_runtime.h>
#include <cstdint>

#define N_NODES 50000
#define N_EDGES 800000
#define R_REL 8
#define NR (N_NODES * R_REL)
#define B_BASES 30
#define D0 128
#define D1 256
#define D2 512
#define BN_EPS 1e-5f
#define ALPHA 0.01f

// ------------------------- scratch (__device__ globals) -------------------------
__device__ int   g_deg[NR];
__device__ int   g_off[NR + 1];
__device__ int   g_cur[NR];
__device__ int   g_bsums[512];
__device__ int   g_boffs[512];
__device__ int   g_ssrc[N_EDGES];
__device__ float g_W1[(size_t)R_REL * D0 * D1];         // [R*128, 256]
__device__ float g_W2[(size_t)R_REL * D1 * D2];         // [R*256, 512]
__device__ float g_agg1[(size_t)NR * D0];               // 204.8 MB
__device__ float g_agg2[(size_t)NR * D1];               // 409.6 MB
__device__ float g_y1[(size_t)N_NODES * D1];
__device__ float g_x1[(size_t)N_NODES * D1];
__device__ float g_y2[(size_t)N_NODES * D2];
__device__ float g_x2[(size_t)N_NODES * D2];
__device__ float g_sum1[D1], g_sumsq1[D1];
__device__ float g_sum2[D2], g_sumsq2[D2];
__device__ float g_scale1[D1], g_shift1[D1];
__device__ float g_scale2[D2], g_shift2[D2];

// ------------------------- small helpers -------------------------
__device__ __forceinline__ uint32_t f2tf32(float x) {
    uint32_t r;
    asm("cvt.rna.tf32.f32 %0, %1;" : "=r"(r) : "f"(x));
    return r;
}

__device__ __forceinline__ void mma_tf32(float (&d)[4], const uint32_t (&a)[4],
                                         const uint32_t (&b)[2]) {
    asm volatile(
        "mma.sync.aligned.m16n8k8.row.col.f32.tf32.tf32.f32 "
        "{%0,%1,%2,%3}, {%4,%5,%6,%7}, {%8,%9}, {%0,%1,%2,%3};"
        : "+f"(d[0]), "+f"(d[1]), "+f"(d[2]), "+f"(d[3])
        : "r"(a[0]), "r"(a[1]), "r"(a[2]), "r"(a[3]), "r"(b[0]), "r"(b[1]));
}

// ------------------------- setup kernels -------------------------
__global__ void zero_k() {
    int i = blockIdx.x * blockDim.x + threadIdx.x;
    int stride = gridDim.x * blockDim.x;
    for (int j = i; j < NR; j += stride) g_deg[j] = 0;
    if (i < D1) { g_sum1[i] = 0.f; g_sumsq1[i] = 0.f; }
    if (i < D2) { g_sum2[i] = 0.f; g_sumsq2[i] = 0.f; }
}

// W_cat[r*Din+i, o] = sum_b comp[r,b] * basis[b,i,o]
__global__ void build_w_k(const float* __restrict__ basis,
                          const float* __restrict__ comp,
                          float* __restrict__ W, int Din, int Dout) {
    __shared__ float sc[R_REL * B_BASES];
    if (threadIdx.x < R_REL * B_BASES) sc[threadIdx.x] = comp[threadIdx.x];
    __syncthreads();
    int idx = blockIdx.x * blockDim.x + threadIdx.x;  // over Din*Dout
    int total = Din * Dout;
    if (idx >= total) return;
    float acc[R_REL];
#pragma unroll
    for (int r = 0; r < R_REL; ++r) acc[r] = 0.f;
    for (int b = 0; b < B_BASES; ++b) {
        float v = basis[(size_t)b * total + idx];
#pragma unroll
        for (int r = 0; r < R_REL; ++r) acc[r] += sc[r * B_BASES + b] * v;
    }
#pragma unroll
    for (int r = 0; r < R_REL; ++r)
        W[(size_t)r * total + idx] = acc[r];
}

__global__ void hist_k(const int* __restrict__ tgt, const int* __restrict__ ety) {
    int e = blockIdx.x * blockDim.x + threadIdx.x;
    if (e < N_EDGES) atomicAdd(&g_deg[tgt[e] * R_REL + ety[e]], 1);
}

__global__ void scan1_k() {
    __shared__ int s[1024];
    int t = threadIdx.x;
    int i = blockIdx.x * 1024 + t;
    int v = (i < NR) ? g_deg[i] : 0;
    s[t] = v;
    __syncthreads();
#pragma unroll
    for (int off = 1; off < 1024; off <<= 1) {
        int u = (t >= off) ? s[t - off] : 0;
        __syncthreads();
        s[t] += u;
        __syncthreads();
    }
    if (i < NR) g_off[i] = s[t] - v;  // block-local exclusive
    if (t == 1023) g_bsums[blockIdx.x] = s[1023];
}

__global__ void scan2_k(int nb) {
    __shared__ int s[512];
    int t = threadIdx.x;
    int v = (t < nb) ? g_bsums[t] : 0;
    s[t] = v;
    __syncthreads();
#pragma unroll
    for (int off = 1; off < 512; off <<= 1) {
        int u = (t >= off) ? s[t - off] : 0;
        __syncthreads();
        s[t] += u;
        __syncthreads();
    }
    g_boffs[t] = s[t] - v;  // exclusive
}

__global__ void scan3_k() {
    int i = blockIdx.x * blockDim.x + threadIdx.x;
    if (i < NR) {
        int o = g_off[i] + g_boffs[i >> 10];
        g_off[i] = o;
        g_cur[i] = o;
    }
    if (i == 0) g_off[NR] = N_EDGES;
}

__global__ void scatter_k(const int* __restrict__ src, const int* __restrict__ tgt,
                          const int* __restrict__ ety) {
    int e = blockIdx.x * blockDim.x + threadIdx.x;
    if (e < N_EDGES) {
        int seg = tgt[e] * R_REL + ety[e];
        int p = atomicAdd(&g_cur[seg], 1);
        g_ssrc[p] = src[e];
    }
}

// ------------------------- aggregation (warp per node) -------------------------
template <int IN4>  // float4 per lane; IN = IN4*128 features
__global__ void __launch_bounds__(256) agg_k(const float* __restrict__ x,
                                             float* __restrict__ agg) {
    int w = (blockIdx.x * blockDim.x + threadIdx.x) >> 5;
    int lane = threadIdx.x & 31;
    if (w >= N_NODES) return;
    int base = w * R_REL;
#pragma unroll 1
    for (int r = 0; r < R_REL; ++r) {
        int s = g_off[base + r];
        int e = g_off[base + r + 1];
        float4 acc[IN4];
#pragma unroll
        for (int i = 0; i < IN4; ++i) acc[i] = make_float4(0.f, 0.f, 0.f, 0.f);
        for (int j = s; j < e; ++j) {
            int sn = g_ssrc[j];
            const float4* row = (const float4*)(x + (size_t)sn * (IN4 * 128));
#pragma unroll
            for (int i = 0; i < IN4; ++i) {
                float4 v = row[lane + 32 * i];
                acc[i].x += v.x; acc[i].y += v.y; acc[i].z += v.z; acc[i].w += v.w;
            }
        }
        float invd = (e > s) ? 1.0f / (float)(e - s) : 0.0f;
        float4* out = (float4*)(agg + (size_t)(base + r) * (IN4 * 128));
#pragma unroll
        for (int i = 0; i < IN4; ++i)
            out[lane + 32 * i] = make_float4(acc[i].x * invd, acc[i].y * invd,
                                             acc[i].z * invd, acc[i].w * invd);
    }
}

// ------------------------- tf32 tensor-core GEMM -------------------------
// C[M,Nn] (= or +=) A[M,K] @ B[K,Nn] (+ bias). Block tile 128x64, ktile 32.
// 8 warps in 4x2; each warp 32x32 via 2x4 m16n8k8 mmas.
template <bool ACCUM, bool BIAS>
__global__ void __launch_bounds__(256) gemm_tf32_k(
    const float* __restrict__ A, const float* __restrict__ Bm,
    const float* __restrict__ bias, float* __restrict__ C,
    int M, int Nn, int K) {
    __shared__ float As[128][36];  // [m][k], stride 36 -> conflict-free frags
    __shared__ float Bs[32][72];   // [k][n], stride 72 -> conflict-free frags

    const int tid = threadIdx.x;
    const int lane = tid & 31, warp = tid >> 5;
    const int wm = warp >> 1, wn = warp & 1;
    const int gid = lane >> 2, tg = lane & 3;
    const int blockN = blockIdx.x * 64;   // N fastest -> A tiles reused in L2
    const int blockM = blockIdx.y * 128;

    float acc[2][4][4];
#pragma unroll
    for (int mt = 0; mt < 2; ++mt)
#pragma unroll
        for (int nt = 0; nt < 4; ++nt)
#pragma unroll
            for (int c = 0; c < 4; ++c) acc[mt][nt][c] = 0.f;

    const int ktiles = K >> 5;
    for (int kt = 0; kt < ktiles; ++kt) {
        // load A tile 128x32 (converted to tf32)
#pragma unroll
        for (int it = 0; it < 4; ++it) {
            int f = tid + it * 256;
            int row = f >> 3, c4 = (f & 7) << 2;
            int gr = blockM + row;
            float4 v = make_float4(0.f, 0.f, 0.f, 0.f);
            if (gr < M) v = *(const float4*)(A + (size_t)gr * K + (kt << 5) + c4);
            float4 w;
            w.x = __uint_as_float(f2tf32(v.x));
            w.y = __uint_as_float(f2tf32(v.y));
            w.z = __uint_as_float(f2tf32(v.z));
            w.w = __uint_as_float(f2tf32(v.w));
            *(float4*)&As[row][c4] = w;
        }
        // load B tile 32x64
#pragma unroll
        for (int it = 0; it < 2; ++it) {
            int f = tid + it * 256;
            int row = f >> 4, c4 = (f & 15) << 2;
            float4 v = *(const float4*)(Bm + (size_t)((kt << 5) + row) * Nn + blockN + c4);
            float4 w;
            w.x = __uint_as_float(f2tf32(v.x));
            w.y = __uint_as_float(f2tf32(v.y));
            w.z = __uint_as_float(f2tf32(v.z));
            w.w = __uint_as_float(f2tf32(v.w));
            *(float4*)&Bs[row][c4] = w;
        }
        __syncthreads();

#pragma unroll
        for (int kk = 0; kk < 4; ++kk) {
            uint32_t a[2][4];
            uint32_t b[4][2];
            int k0 = kk * 8 + tg;
#pragma unroll
            for (int mt = 0; mt < 2; ++mt) {
                int r0 = wm * 32 + mt * 16 + gid;
                a[mt][0] = __float_as_uint(As[r0][k0]);
                a[mt][1] = __float_as_uint(As[r0 + 8][k0]);
                a[mt][2] = __float_as_uint(As[r0][k0 + 4]);
                a[mt][3] = __float_as_uint(As[r0 + 8][k0 + 4]);
            }
#pragma unroll
            for (int nt = 0; nt < 4; ++nt) {
                int c0 = wn * 32 + nt * 8 + gid;
                b[nt][0] = __float_as_uint(Bs[k0][c0]);
                b[nt][1] = __float_as_uint(Bs[k0 + 4][c0]);
            }
#pragma unroll
            for (int mt = 0; mt < 2; ++mt)
#pragma unroll
                for (int nt = 0; nt < 4; ++nt) mma_tf32(acc[mt][nt], a[mt], b[nt]);
        }
        __syncthreads();
    }

    // epilogue
#pragma unroll
    for (int mt = 0; mt < 2; ++mt)
#pragma unroll
        for (int nt = 0; nt < 4; ++nt) {
            int row0 = blockM + wm * 32 + mt * 16 + gid;
            int col = blockN + wn * 32 + nt * 8 + 2 * tg;
            float bx = 0.f, by = 0.f;
            if (BIAS) { bx = bias[col]; by = bias[col + 1]; }
            if (row0 < M) {
                float* p = C + (size_t)row0 * Nn + col;
                float2 o = make_float2(acc[mt][nt][0] + bx, acc[mt][nt][1] + by);
                if (ACCUM) { float2 old = *(float2*)p; o.x += old.x; o.y += old.y; }
                *(float2*)p = o;
            }
            int row1 = row0 + 8;
            if (row1 < M) {
                float* p = C + (size_t)row1 * Nn + col;
                float2 o = make_float2(acc[mt][nt][2] + bx, acc[mt][nt][3] + by);
                if (ACCUM) { float2 old = *(float2*)p; o.x += old.x; o.y += old.y; }
                *(float2*)p = o;
            }
        }
}

// ------------------------- batchnorm -------------------------
__global__ void bnstats_k(const float* __restrict__ y, int C,
                          float* __restrict__ sum, float* __restrict__ sumsq) {
    int c = blockIdx.x * blockDim.x + threadIdx.x;  // C multiple of 256
    float s = 0.f, q = 0.f;
    for (int row = blockIdx.y; row < N_NODES; row += gridDim.y) {
        float v = y[(size_t)row * C + c];
        s += v;
        q += v * v;
    }
    atomicAdd(&sum[c], s);
    atomicAdd(&sumsq[c], q);
}

__global__ void bnfin_k(const float* __restrict__ sum, const float* __restrict__ sumsq,
                        const float* __restrict__ gamma, const float* __restrict__ beta,
                        float* __restrict__ scale, float* __restrict__ shift, int C) {
    int c = blockIdx.x * blockDim.x + threadIdx.x;
    if (c >= C) return;
    const float invn = 1.0f / (float)N_NODES;
    float mu = sum[c] * invn;
    float var = sumsq[c] * invn - mu * mu;
    float sc = gamma[c] * rsqrtf(var + BN_EPS);
    scale[c] = sc;
    shift[c] = beta[c] - mu * sc;
}

__global__ void bnapply_k(const float* __restrict__ y, const float* __restrict__ scale,
                          const float* __restrict__ shift, float* __restrict__ x, int C) {
    size_t total = (size_t)N_NODES * C;
    size_t stride = (size_t)gridDim.x * blockDim.x;
    for (size_t i = blockIdx.x * (size_t)blockDim.x + threadIdx.x; i < total; i += stride) {
        int c = (int)(i % C);
        float v = y[i] * scale[c] + shift[c];
        x[i] = v > 0.f ? v : ALPHA * v;
    }
}

// ------------------------- host launch -------------------------
extern "C" void kernel_launch(void* const* d_in, const int* in_sizes, int n_in,
                              void* d_out, int out_size) {
    const float* emb    = (const float*)d_in[0];
    const int*   eidx   = (const int*)d_in[1];
    const int*   ety    = (const int*)d_in[2];
    const float* basis1 = (const float*)d_in[3];
    const float* comp1  = (const float*)d_in[4];
    const float* root1  = (const float*)d_in[5];
    const float* bias1  = (const float*)d_in[6];
    const float* gamma1 = (const float*)d_in[7];
    const float* beta1  = (const float*)d_in[8];
    const float* basis2 = (const float*)d_in[9];
    const float* comp2  = (const float*)d_in[10];
    const float* root2  = (const float*)d_in[11];
    const float* bias2  = (const float*)d_in[12];
    const float* gamma2 = (const float*)d_in[13];
    const float* beta2  = (const float*)d_in[14];
    const float* Wf     = (const float*)d_in[15];
    const float* bf     = (const float*)d_in[16];
    const int* srcp = eidx;
    const int* tgtp = eidx + N_EDGES;
    float* outp = (float*)d_out;

    float *W1, *W2, *agg1, *agg2, *y1, *x1, *y2, *x2;
    float *sum1, *sumsq1, *sum2, *sumsq2, *scale1, *shift1, *scale2, *shift2;
    cudaGetSymbolAddress((void**)&W1, g_W1);
    cudaGetSymbolAddress((void**)&W2, g_W2);
    cudaGetSymbolAddress((void**)&agg1, g_agg1);
    cudaGetSymbolAddress((void**)&agg2, g_agg2);
    cudaGetSymbolAddress((void**)&y1, g_y1);
    cudaGetSymbolAddress((void**)&x1, g_x1);
    cudaGetSymbolAddress((void**)&y2, g_y2);
    cudaGetSymbolAddress((void**)&x2, g_x2);
    cudaGetSymbolAddress((void**)&sum1, g_sum1);
    cudaGetSymbolAddress((void**)&sumsq1, g_sumsq1);
    cudaGetSymbolAddress((void**)&sum2, g_sum2);
    cudaGetSymbolAddress((void**)&sumsq2, g_sumsq2);
    cudaGetSymbolAddress((void**)&scale1, g_scale1);
    cudaGetSymbolAddress((void**)&shift1, g_shift1);
    cudaGetSymbolAddress((void**)&scale2, g_scale2);
    cudaGetSymbolAddress((void**)&shift2, g_shift2);

    const int TPB = 256;
    int nScanBlocks = (NR + 1023) / 1024;  // 391

    // setup
    zero_k<<<512, TPB>>>();
    build_w_k<<<(D0 * D1 + TPB - 1) / TPB, TPB>>>(basis1, comp1, W1, D0, D1);
    build_w_k<<<(D1 * D2 + TPB - 1) / TPB, TPB>>>(basis2, comp2, W2, D1, D2);
    hist_k<<<(N_EDGES + TPB - 1) / TPB, TPB>>>(tgtp, ety);
    scan1_k<<<nScanBlocks, 1024>>>();
    scan2_k<<<1, 512>>>(nScanBlocks);
    scan3_k<<<(NR + TPB - 1) / TPB, TPB>>>();
    scatter_k<<<(N_EDGES + TPB - 1) / TPB, TPB>>>(srcp, tgtp, ety);

    dim3 gemmGrid1(D1 / 64, (N_NODES + 127) / 128);
    dim3 gemmGrid2(D2 / 64, (N_NODES + 127) / 128);

    // layer 1
    agg_k<1><<<(N_NODES * 32 + TPB - 1) / TPB, TPB>>>(emb, agg1);
    gemm_tf32_k<false, true><<<gemmGrid1, TPB>>>(agg1, W1, bias1, y1,
                                                 N_NODES, D1, R_REL * D0);
    gemm_tf32_k<true, false><<<gemmGrid1, TPB>>>(emb, root1, nullptr, y1,
                                                 N_NODES, D1, D0);
    bnstats_k<<<dim3(D1 / TPB, 128), TPB>>>(y1, D1, sum1, sumsq1);
    bnfin_k<<<1, D1>>>(sum1, sumsq1, gamma1, beta1, scale1, shift1, D1);
    bnapply_k<<<8192, TPB>>>(y1, scale1, shift1, x1, D1);

    // layer 2
    agg_k<2><<<(N_NODES * 32 + TPB - 1) / TPB, TPB>>>(x1, agg2);
    gemm_tf32_k<false, true><<<gemmGrid2, TPB>>>(agg2, W2, bias2, y2,
                                                 N_NODES, D2, R_REL * D1);
    gemm_tf32_k<true, false><<<gemmGrid2, TPB>>>(x1, root2, nullptr, y2,
                                                 N_NODES, D2, D1);
    bnstats_k<<<dim3(D2 / TPB, 128), TPB>>>(y2, D2, sum2, sumsq2);
    bnfin_k<<<1, D2>>>(sum2, sumsq2, gamma2, beta2, scale2, shift2, D2);
    bnapply_k<<<8192, TPB>>>(y2, scale2, shift2, x2, D2);

    // final linear
    gemm_tf32_k<false, true><<<gemmGrid2, TPB>>>(x2, Wf, bf, outp,
                                                 N_NODES, D2, D2);
}

// round 3
// speedup vs baseline: 1.3577x; 1.3577x over previous
#include <cuda_runtime.h>
#include <cstdint>

#define N_NODES 50000
#define N_EDGES 800000
#define R_REL 8
#define NR (N_NODES * R_REL)
#define B_BASES 30
#define D0 128
#define D1 256
#define D2 512
#define K1 ((R_REL + 1) * D0)   // 1152
#define K2 ((R_REL + 1) * D1)   // 2304
#define BN_EPS 1e-5f
#define ALPHA 0.01f

// ------------------------- scratch (__device__ globals) -------------------------
__device__ int   g_deg[NR];
__device__ int   g_off[NR + 1];
__device__ int   g_cur[NR];
__device__ int   g_bsums[512];
__device__ int   g_boffs[512];
__device__ int   g_ssrc[N_EDGES];
__device__ float g_W1[(size_t)K1 * D1];                 // [(R+1)*128, 256]
__device__ float g_W2[(size_t)K2 * D2];                 // [(R+1)*256, 512]
__device__ float g_Wf[(size_t)D2 * D2];                 // tf32 copy of Wf
__device__ float g_agg1[(size_t)N_NODES * K1];          // 230 MB
__device__ float g_agg2[(size_t)N_NODES * K2];          // 461 MB
__device__ float g_y1[(size_t)N_NODES * D1];
__device__ float g_x1[(size_t)N_NODES * D1];
__device__ float g_y2[(size_t)N_NODES * D2];
__device__ float g_x2[(size_t)N_NODES * D2];
__device__ float g_sum1[D1], g_sumsq1[D1];
__device__ float g_sum2[D2], g_sumsq2[D2];
__device__ float g_scale1[D1], g_shift1[D1];
__device__ float g_scale2[D2], g_shift2[D2];

// ------------------------- small helpers -------------------------
__device__ __forceinline__ float f2tf32f(float x) {
    uint32_t r;
    asm("cvt.rna.tf32.f32 %0, %1;" : "=r"(r) : "f"(x));
    return __uint_as_float(r);
}

__device__ __forceinline__ float4 tf4(float4 v) {
    return make_float4(f2tf32f(v.x), f2tf32f(v.y), f2tf32f(v.z), f2tf32f(v.w));
}

__device__ __forceinline__ void mma_tf32(float (&d)[4], const float (&a)[4],
                                         const float (&b)[2]) {
    asm volatile(
        "mma.sync.aligned.m16n8k8.row.col.f32.tf32.tf32.f32 "
        "{%0,%1,%2,%3}, {%4,%5,%6,%7}, {%8,%9}, {%0,%1,%2,%3};"
        : "+f"(d[0]), "+f"(d[1]), "+f"(d[2]), "+f"(d[3])
        : "r"(__float_as_uint(a[0])), "r"(__float_as_uint(a[1])),
          "r"(__float_as_uint(a[2])), "r"(__float_as_uint(a[3])),
          "r"(__float_as_uint(b[0])), "r"(__float_as_uint(b[1])));
}

__device__ __forceinline__ void cp_async16(void* smem, const void* gmem, int src_bytes) {
    uint32_t s = (uint32_t)__cvta_generic_to_shared(smem);
    asm volatile("cp.async.cg.shared.global [%0], [%1], 16, %2;"
                 :: "r"(s), "l"(gmem), "r"(src_bytes));
}
__device__ __forceinline__ void cp_commit() {
    asm volatile("cp.async.commit_group;");
}

// ------------------------- setup kernels -------------------------
__global__ void zero_k() {
    int i = blockIdx.x * blockDim.x + threadIdx.x;
    int stride = gridDim.x * blockDim.x;
    for (int j = i; j < NR; j += stride) g_deg[j] = 0;
    if (i < D1) { g_sum1[i] = 0.f; g_sumsq1[i] = 0.f; }
    if (i < D2) { g_sum2[i] = 0.f; g_sumsq2[i] = 0.f; }
}

// W_cat[(r*Din+i)*Dout+o] = tf32( sum_b comp[r,b] * basis[b,i,o] )
__global__ void build_w_k(const float* __restrict__ basis,
                          const float* __restrict__ comp,
                          float* __restrict__ W, int Din, int Dout) {
    __shared__ float sc[R_REL * B_BASES];
    if (threadIdx.x < R_REL * B_BASES) sc[threadIdx.x] = comp[threadIdx.x];
    __syncthreads();
    int idx = blockIdx.x * blockDim.x + threadIdx.x;  // over Din*Dout
    int total = Din * Dout;
    if (idx >= total) return;
    float acc[R_REL];
#pragma unroll
    for (int r = 0; r < R_REL; ++r) acc[r] = 0.f;
    for (int b = 0; b < B_BASES; ++b) {
        float v = basis[(size_t)b * total + idx];
#pragma unroll
        for (int r = 0; r < R_REL; ++r) acc[r] += sc[r * B_BASES + b] * v;
    }
#pragma unroll
    for (int r = 0; r < R_REL; ++r)
        W[(size_t)r * total + idx] = f2tf32f(acc[r]);
}

// append root into rows [R*Din, (R+1)*Din)
__global__ void copy_root_k(const float* __restrict__ root, float* __restrict__ W,
                            int Din, int Dout) {
    int idx = blockIdx.x * blockDim.x + threadIdx.x;
    int total = Din * Dout;
    if (idx < total) W[(size_t)R_REL * total + idx] = f2tf32f(root[idx]);
}

__global__ void conv_k(const float* __restrict__ src, float* __restrict__ dst, int n) {
    int i = blockIdx.x * blockDim.x + threadIdx.x;
    if (i < n) dst[i] = f2tf32f(src[i]);
}

__global__ void hist_k(const int* __restrict__ tgt, const int* __restrict__ ety) {
    int e = blockIdx.x * blockDim.x + threadIdx.x;
    if (e < N_EDGES) atomicAdd(&g_deg[tgt[e] * R_REL + ety[e]], 1);
}

__global__ void scan1_k() {
    __shared__ int s[1024];
    int t = threadIdx.x;
    int i = blockIdx.x * 1024 + t;
    int v = (i < NR) ? g_deg[i] : 0;
    s[t] = v;
    __syncthreads();
#pragma unroll
    for (int off = 1; off < 1024; off <<= 1) {
        int u = (t >= off) ? s[t - off] : 0;
        __syncthreads();
        s[t] += u;
        __syncthreads();
    }
    if (i < NR) g_off[i] = s[t] - v;  // block-local exclusive
    if (t == 1023) g_bsums[blockIdx.x] = s[1023];
}

__global__ void scan2_k(int nb) {
    __shared__ int s[512];
    int t = threadIdx.x;
    int v = (t < nb) ? g_bsums[t] : 0;
    s[t] = v;
    __syncthreads();
#pragma unroll
    for (int off = 1; off < 512; off <<= 1) {
        int u = (t >= off) ? s[t - off] : 0;
        __syncthreads();
        s[t] += u;
        __syncthreads();
    }
    g_boffs[t] = s[t] - v;  // exclusive
}

__global__ void scan3_k() {
    int i = blockIdx.x * blockDim.x + threadIdx.x;
    if (i < NR) {
        int o = g_off[i] + g_boffs[i >> 10];
        g_off[i] = o;
        g_cur[i] = o;
    }
    if (i == 0) g_off[NR] = N_EDGES;
}

__global__ void scatter_k(const int* __restrict__ src, const int* __restrict__ tgt,
                          const int* __restrict__ ety) {
    int e = blockIdx.x * blockDim.x + threadIdx.x;
    if (e < N_EDGES) {
        int seg = tgt[e] * R_REL + ety[e];
        int p = atomicAdd(&g_cur[seg], 1);
        g_ssrc[p] = src[e];
    }
}

// ------------------------- aggregation (warp per node) -------------------------
// Writes A rows of (R+1)*Din: [mean_r0 | ... | mean_r7 | x_self], tf32-rounded.
template <int IN4>  // float4 per lane; Din = IN4*128
__global__ void __launch_bounds__(256) agg_k(const float* __restrict__ x,
                                             float* __restrict__ agg) {
    const int Din = IN4 * 128;
    int w = (blockIdx.x * blockDim.x + threadIdx.x) >> 5;
    int lane = threadIdx.x & 31;
    if (w >= N_NODES) return;
    int base = w * R_REL;
    float* rowbase = agg + (size_t)w * ((R_REL + 1) * Din);
#pragma unroll 1
    for (int r = 0; r < R_REL; ++r) {
        int s = g_off[base + r];
        int e = g_off[base + r + 1];
        float4 acc[IN4];
#pragma unroll
        for (int i = 0; i < IN4; ++i) acc[i] = make_float4(0.f, 0.f, 0.f, 0.f);
        for (int j = s; j < e; ++j) {
            int sn = g_ssrc[j];
            const float4* row = (const float4*)(x + (size_t)sn * Din);
#pragma unroll
            for (int i = 0; i < IN4; ++i) {
                float4 v = row[lane + 32 * i];
                acc[i].x += v.x; acc[i].y += v.y; acc[i].z += v.z; acc[i].w += v.w;
            }
        }
        float invd = (e > s) ? 1.0f / (float)(e - s) : 0.0f;
        float4* out = (float4*)(rowbase + r * Din);
#pragma unroll
        for (int i = 0; i < IN4; ++i)
            out[lane + 32 * i] = tf4(make_float4(acc[i].x * invd, acc[i].y * invd,
                                                 acc[i].z * invd, acc[i].w * invd));
    }
    // self-feature slot (root term), tf32-rounded
    {
        const float4* srow = (const float4*)(x + (size_t)w * Din);
        float4* out = (float4*)(rowbase + R_REL * Din);
#pragma unroll
        for (int i = 0; i < IN4; ++i) out[lane + 32 * i] = tf4(srow[lane + 32 * i]);
    }
}

// ------------------------- pipelined tf32 tensor-core GEMM -------------------------
// C[M,Nn] = A[M,K] @ B[K,Nn] + bias. Inputs pre-rounded to tf32 bit patterns.
// Block tile 128x128, BK=16, 2-stage cp.async double buffer.
// 4 warps (2x2), warp tile 64x64 via m16n8k8.
__global__ void __launch_bounds__(128, 2) gemm_k(
    const float* __restrict__ A, const float* __restrict__ Bm,
    const float* __restrict__ bias, float* __restrict__ C,
    int M, int Nn, int K) {
    __shared__ float As[2][128][20];   // pad 20: conflict-free frag loads
    __shared__ float Bs[2][16][136];   // pad 136 (mod32=8): conflict-free

    const int tid = threadIdx.x;
    const int lane = tid & 31, warp = tid >> 5;
    const int wm = warp >> 1, wn = warp & 1;
    const int gid = lane >> 2, tg = lane & 3;
    const int blockN = blockIdx.x * 128;
    const int blockM = blockIdx.y * 128;

    float acc[4][8][4];
#pragma unroll
    for (int mt = 0; mt < 4; ++mt)
#pragma unroll
        for (int nt = 0; nt < 8; ++nt)
#pragma unroll
            for (int c = 0; c < 4; ++c) acc[mt][nt][c] = 0.f;

    const int ktiles = K >> 4;

    // stage loader
    auto load_stage = [&](int st, int kt) {
        int kbase = kt << 4;
#pragma unroll
        for (int it = 0; it < 4; ++it) {
            int idx = tid + it * 128;
            int arow = idx >> 2, ac4 = (idx & 3) << 2;
            const float* src = A + (size_t)(blockM + arow) * K + kbase + ac4;
            cp_async16(&As[st][arow][ac4], src, (blockM + arow) < M ? 16 : 0);
        }
#pragma unroll
        for (int it = 0; it < 4; ++it) {
            int idx = tid + it * 128;
            int brow = idx >> 5, bc4 = (idx & 31) << 2;
            const float* src = Bm + (size_t)(kbase + brow) * Nn + blockN + bc4;
            cp_async16(&Bs[st][brow][bc4], src, 16);
        }
        cp_commit();
    };

    load_stage(0, 0);

    for (int kt = 0; kt < ktiles; ++kt) {
        int cur = kt & 1;
        if (kt + 1 < ktiles) {
            load_stage(cur ^ 1, kt + 1);
            asm volatile("cp.async.wait_group 1;");
        } else {
            asm volatile("cp.async.wait_group 0;");
        }
        __syncthreads();

#pragma unroll
        for (int kk = 0; kk < 2; ++kk) {
            int k0 = kk * 8 + tg;
            float a[4][4];
#pragma unroll
            for (int mt = 0; mt < 4; ++mt) {
                int r0 = wm * 64 + mt * 16 + gid;
                a[mt][0] = As[cur][r0][k0];
                a[mt][1] = As[cur][r0 + 8][k0];
                a[mt][2] = As[cur][r0][k0 + 4];
                a[mt][3] = As[cur][r0 + 8][k0 + 4];
            }
            float b[8][2];
#pragma unroll
            for (int nt = 0; nt < 8; ++nt) {
                int c0 = wn * 64 + nt * 8 + gid;
                b[nt][0] = Bs[cur][k0][c0];
                b[nt][1] = Bs[cur][k0 + 4][c0];
            }
#pragma unroll
            for (int mt = 0; mt < 4; ++mt)
#pragma unroll
                for (int nt = 0; nt < 8; ++nt) mma_tf32(acc[mt][nt], a[mt], b[nt]);
        }
        __syncthreads();
    }

    // epilogue: bias + store
#pragma unroll
    for (int mt = 0; mt < 4; ++mt)
#pragma unroll
        for (int nt = 0; nt < 8; ++nt) {
            int row0 = blockM + wm * 64 + mt * 16 + gid;
            int col = blockN + wn * 64 + nt * 8 + 2 * tg;
            float bx = bias[col], by = bias[col + 1];
            if (row0 < M) {
                float2 o = make_float2(acc[mt][nt][0] + bx, acc[mt][nt][1] + by);
                *(float2*)(C + (size_t)row0 * Nn + col) = o;
            }
            int row1 = row0 + 8;
            if (row1 < M) {
                float2 o = make_float2(acc[mt][nt][2] + bx, acc[mt][nt][3] + by);
                *(float2*)(C + (size_t)row1 * Nn + col) = o;
            }
        }
}

// ------------------------- batchnorm -------------------------
__global__ void bnstats_k(const float* __restrict__ y, int C,
                          float* __restrict__ sum, float* __restrict__ sumsq) {
    int c = blockIdx.x * blockDim.x + threadIdx.x;  // C multiple of 256
    float s = 0.f, q = 0.f;
    for (int row = blockIdx.y; row < N_NODES; row += gridDim.y) {
        float v = y[(size_t)row * C + c];
        s += v;
        q += v * v;
    }
    atomicAdd(&sum[c], s);
    atomicAdd(&sumsq[c], q);
}

__global__ void bnfin_k(const float* __restrict__ sum, const float* __restrict__ sumsq,
                        const float* __restrict__ gamma, const float* __restrict__ beta,
                        float* __restrict__ scale, float* __restrict__ shift, int C) {
    int c = blockIdx.x * blockDim.x + threadIdx.x;
    if (c >= C) return;
    const float invn = 1.0f / (float)N_NODES;
    float mu = sum[c] * invn;
    float var = sumsq[c] * invn - mu * mu;
    float sc = gamma[c] * rsqrtf(var + BN_EPS);
    scale[c] = sc;
    shift[c] = beta[c] - mu * sc;
}

// BN + LeakyReLU, output tf32-rounded (feeds GEMM A / aggregation)
__global__ void bnapply_k(const float* __restrict__ y, const float* __restrict__ scale,
                          const float* __restrict__ shift, float* __restrict__ x, int C) {
    size_t total = (size_t)N_NODES * C;
    size_t stride = (size_t)gridDim.x * blockDim.x;
    for (size_t i = blockIdx.x * (size_t)blockDim.x + threadIdx.x; i < total; i += stride) {
        int c = (int)(i % C);
        float v = y[i] * scale[c] + shift[c];
        v = v > 0.f ? v : ALPHA * v;
        x[i] = f2tf32f(v);
    }
}

// ------------------------- host launch -------------------------
extern "C" void kernel_launch(void* const* d_in, const int* in_sizes, int n_in,
                              void* d_out, int out_size) {
    const float* emb    = (const float*)d_in[0];
    const int*   eidx   = (const int*)d_in[1];
    const int*   ety    = (const int*)d_in[2];
    const float* basis1 = (const float*)d_in[3];
    const float* comp1  = (const float*)d_in[4];
    const float* root1  = (const float*)d_in[5];
    const float* bias1  = (const float*)d_in[6];
    const float* gamma1 = (const float*)d_in[7];
    const float* beta1  = (const float*)d_in[8];
    const float* basis2 = (const float*)d_in[9];
    const float* comp2  = (const float*)d_in[10];
    const float* root2  = (const float*)d_in[11];
    const float* bias2  = (const float*)d_in[12];
    const float* gamma2 = (const float*)d_in[13];
    const float* beta2  = (const float*)d_in[14];
    const float* Wf     = (const float*)d_in[15];
    const float* bf     = (const float*)d_in[16];
    const int* srcp = eidx;
    const int* tgtp = eidx + N_EDGES;
    float* outp = (float*)d_out;

    float *W1, *W2, *Wfc, *agg1, *agg2, *y1, *x1, *y2, *x2;
    float *sum1, *sumsq1, *sum2, *sumsq2, *scale1, *shift1, *scale2, *shift2;
    cudaGetSymbolAddress((void**)&W1, g_W1);
    cudaGetSymbolAddress((void**)&W2, g_W2);
    cudaGetSymbolAddress((void**)&Wfc, g_Wf);
    cudaGetSymbolAddress((void**)&agg1, g_agg1);
    cudaGetSymbolAddress((void**)&agg2, g_agg2);
    cudaGetSymbolAddress((void**)&y1, g_y1);
    cudaGetSymbolAddress((void**)&x1, g_x1);
    cudaGetSymbolAddress((void**)&y2, g_y2);
    cudaGetSymbolAddress((void**)&x2, g_x2);
    cudaGetSymbolAddress((void**)&sum1, g_sum1);
    cudaGetSymbolAddress((void**)&sumsq1, g_sumsq1);
    cudaGetSymbolAddress((void**)&sum2, g_sum2);
    cudaGetSymbolAddress((void**)&sumsq2, g_sumsq2);
    cudaGetSymbolAddress((void**)&scale1, g_scale1);
    cudaGetSymbolAddress((void**)&shift1, g_shift1);
    cudaGetSymbolAddress((void**)&scale2, g_scale2);
    cudaGetSymbolAddress((void**)&shift2, g_shift2);

    const int TPB = 256;
    int nScanBlocks = (NR + 1023) / 1024;  // 391

    // setup
    zero_k<<<512, TPB>>>();
    build_w_k<<<(D0 * D1 + TPB - 1) / TPB, TPB>>>(basis1, comp1, W1, D0, D1);
    build_w_k<<<(D1 * D2 + TPB - 1) / TPB, TPB>>>(basis2, comp2, W2, D1, D2);
    copy_root_k<<<(D0 * D1 + TPB - 1) / TPB, TPB>>>(root1, W1, D0, D1);
    copy_root_k<<<(D1 * D2 + TPB - 1) / TPB, TPB>>>(root2, W2, D1, D2);
    conv_k<<<(D2 * D2 + TPB - 1) / TPB, TPB>>>(Wf, Wfc, D2 * D2);
    hist_k<<<(N_EDGES + TPB - 1) / TPB, TPB>>>(tgtp, ety);
    scan1_k<<<nScanBlocks, 1024>>>();
    scan2_k<<<1, 512>>>(nScanBlocks);
    scan3_k<<<(NR + TPB - 1) / TPB, TPB>>>();
    scatter_k<<<(N_EDGES + TPB - 1) / TPB, TPB>>>(srcp, tgtp, ety);

    dim3 gemmGrid1(D1 / 128, (N_NODES + 127) / 128);
    dim3 gemmGrid2(D2 / 128, (N_NODES + 127) / 128);

    // layer 1: fused [agg | self] GEMM -> BN -> LeakyReLU
    agg_k<1><<<(N_NODES * 32 + TPB - 1) / TPB, TPB>>>(emb, agg1);
    gemm_k<<<gemmGrid1, 128>>>(agg1, W1, bias1, y1, N_NODES, D1, K1);
    bnstats_k<<<dim3(D1 / TPB, 128), TPB>>>(y1, D1, sum1, sumsq1);
    bnfin_k<<<1, D1>>>(sum1, sumsq1, gamma1, beta1, scale1, shift1, D1);
    bnapply_k<<<8192, TPB>>>(y1, scale1, shift1, x1, D1);

    // layer 2
    agg_k<2><<<(N_NODES * 32 + TPB - 1) / TPB, TPB>>>(x1, agg2);
    gemm_k<<<gemmGrid2, 128>>>(agg2, W2, bias2, y2, N_NODES, D2, K2);
    bnstats_k<<<dim3(D2 / TPB, 128), TPB>>>(y2, D2, sum2, sumsq2);
    bnfin_k<<<1, D2>>>(sum2, sumsq2, gamma2, beta2, scale2, shift2, D2);
    bnapply_k<<<8192, TPB>>>(y2, scale2, shift2, x2, D2);

    // final linear
    gemm_k<<<gemmGrid2, 128>>>(x2, Wfc, bf, outp, N_NODES, D2, D2);
}